// round 15
// baseline (speedup 1.0000x reference)
#include <cuda_runtime.h>
#include <cuda_bf16.h>
#include <cstdint>
#include <math.h>

#define B_DIM 8
#define L_DIM 2048
#define D_DIM 256
#define NROW (B_DIM * L_DIM)

#define BM 64
#define BN 32
#define NTILE (L_DIM / BN)   // 64
#define ATH 128
#define L2E 1.44269504f
#define NEG_C (-57.7078016f)

// smem layout (total 112896 B = 110.25 KB -> 2 CTAs/SM)
#define SQH 0          // Q hi: 64 x 512B   (tail stage1 lives here after c=7)
#define SQL 32768      // Q lo
#define SKH 65536      // K hi 32x512 / tail stage0 W hi
#define SKL 81920      // K lo            / tail stage0 W lo
#define SMSK 98304     // 64 ballot words
#define SG   98560     // gates 3x256 f32
#define SBF  101632    // bf 256 f32
#define SA_H 102656    // tail stage0 A hi: 64 x 80B
#define SA_L 107776    // tail stage0 A lo
#define ATT_SMEM 112896

// tail stage1 (carved from dead Q region, c >= 8)
#define ST1_WH 0
#define ST1_WL 16384
#define ST1_AH 32768
#define ST1_AL 37888

__device__ float g_ga[D_DIM];
__device__ float g_gb[D_DIM];
__device__ float g_gc[D_DIM];
__device__ __nv_bfloat16 g_Wch[3 * D_DIM * D_DIM];
__device__ __nv_bfloat16 g_Wcl[3 * D_DIM * D_DIM];
__device__ __nv_bfloat16 g_c1h[(size_t)NROW * D_DIM];
__device__ __nv_bfloat16 g_c1l[(size_t)NROW * D_DIM];
__device__ __nv_bfloat16 g_augh[(size_t)NROW * D_DIM];
__device__ __nv_bfloat16 g_augl[(size_t)NROW * D_DIM];
__device__ __nv_bfloat16 g_prodh[(size_t)NROW * D_DIM];
__device__ __nv_bfloat16 g_prodl[(size_t)NROW * D_DIM];

__device__ __forceinline__ uint32_t smem_u32(const void* p) {
    uint32_t a;
    asm("{ .reg .u64 t; cvta.to.shared.u64 t, %1; cvt.u32.u64 %0, t; }" : "=r"(a) : "l"(p));
    return a;
}
#define CP16(dst, src) asm volatile("cp.async.cg.shared.global [%0], [%1], 16;" :: "r"(dst), "l"(src))
#define CP_COMMIT()    asm volatile("cp.async.commit_group;" ::: "memory")
#define CP_WAIT(n)     asm volatile("cp.async.wait_group %0;" :: "n"(n) : "memory")

__device__ __forceinline__ void ldsm4(uint32_t addr, uint32_t r[4]) {
    asm volatile("ldmatrix.sync.aligned.m8n8.x4.shared.b16 {%0,%1,%2,%3}, [%4];"
        : "=r"(r[0]), "=r"(r[1]), "=r"(r[2]), "=r"(r[3]) : "r"(addr));
}
__device__ __forceinline__ void ldsm4t(uint32_t addr, uint32_t r[4]) {
    asm volatile("ldmatrix.sync.aligned.m8n8.x4.trans.shared.b16 {%0,%1,%2,%3}, [%4];"
        : "=r"(r[0]), "=r"(r[1]), "=r"(r[2]), "=r"(r[3]) : "r"(addr));
}
__device__ __forceinline__ void mma16816(float d[4], const uint32_t a[4], const uint32_t b[2]) {
    asm volatile(
        "mma.sync.aligned.m16n8k16.row.col.f32.bf16.bf16.f32 "
        "{%0,%1,%2,%3}, {%4,%5,%6,%7}, {%8,%9}, {%0,%1,%2,%3};"
        : "+f"(d[0]), "+f"(d[1]), "+f"(d[2]), "+f"(d[3])
        : "r"(a[0]), "r"(a[1]), "r"(a[2]), "r"(a[3]), "r"(b[0]), "r"(b[1]));
}
__device__ __forceinline__ float fast_ex2(float x) {
    float r;
    asm("ex2.approx.f32 %0, %1;" : "=f"(r) : "f"(x));
    return r;
}
__device__ __forceinline__ uint32_t packbf(float hi, float lo) {
    uint32_t d;
    asm("cvt.rn.bf16x2.f32 %0, %1, %2;" : "=r"(d) : "f"(hi), "f"(lo));
    return d;
}

// ---------------- merged prep + convert (one launch) ----------------
#define CONV_BLOCKS (NROW * D_DIM / 4 / 256)   // 4096
__global__ void prep_convert(const float* __restrict__ Wf, const float* __restrict__ Wg,
                             const float* __restrict__ c1)
{
    if (blockIdx.x < CONV_BLOCKS) {
        int k = blockIdx.x * 256 + threadIdx.x;
        float4 v = ((const float4*)c1)[k];
        __nv_bfloat162* oh = (__nv_bfloat162*)g_c1h;
        __nv_bfloat162* ol = (__nv_bfloat162*)g_c1l;
        __nv_bfloat16 h0 = __float2bfloat16(v.x), h1 = __float2bfloat16(v.y);
        __nv_bfloat16 h2 = __float2bfloat16(v.z), h3 = __float2bfloat16(v.w);
        oh[k * 2]     = __nv_bfloat162(h0, h1);
        oh[k * 2 + 1] = __nv_bfloat162(h2, h3);
        ol[k * 2]     = __nv_bfloat162(__float2bfloat16(v.x - __bfloat162float(h0)),
                                       __float2bfloat16(v.y - __bfloat162float(h1)));
        ol[k * 2 + 1] = __nv_bfloat162(__float2bfloat16(v.z - __bfloat162float(h2)),
                                       __float2bfloat16(v.w - __bfloat162float(h3)));
        return;
    }
    int i = (blockIdx.x - CONV_BLOCKS) * 256 + threadIdx.x;
    if (i < D_DIM * D_DIM) {
        int k = i >> 8, d = i & 255;
        float w4 = Wf[(size_t)(768 + k) * D_DIM + d];
        float wa = Wf[(size_t)k * D_DIM + d] + w4;
        float wb = Wf[(size_t)(256 + k) * D_DIM + d] - w4;
        float wc = Wf[(size_t)(512 + k) * D_DIM + d];
        float w3[3] = {wa, wb, wc};
        #pragma unroll
        for (int tmc = 0; tmc < 3; tmc++) {
            __nv_bfloat16 h = __float2bfloat16(w3[tmc]);
            size_t o = (size_t)(tmc * D_DIM + k) * D_DIM + d;
            g_Wch[o] = h;
            g_Wcl[o] = __float2bfloat16(w3[tmc] - __bfloat162float(h));
        }
    }
    if (i < D_DIM) {
        float v4 = Wg[768 + i];
        g_ga[i] = Wg[i] + v4;
        g_gb[i] = Wg[256 + i] - v4;
        g_gc[i] = Wg[512 + i];
    }
}

// ---------------- loaders ----------------
// K tile: 32 keys x 512B hi + lo = 2048 x 16B chunks, 16 iters of 128 thr
__device__ __forceinline__ void k_issue(uint32_t sb, int j0, int tid,
                                        const __nv_bfloat16* k1h, const __nv_bfloat16* k1l)
{
    #pragma unroll
    for (int it = 0; it < 16; it++) {
        int chunk = it * ATH + tid;
        int hl = chunk >> 10;
        int rem = chunk & 1023;
        int row = rem >> 5, ch = rem & 31;
        const __nv_bfloat16* src = (hl ? k1l : k1h) + ((size_t)(j0 + row)) * D_DIM + ch * 8;
        CP16(sb + (hl ? SKL : SKH) + row * 512 + ((ch ^ (row & 7)) << 4), src);
    }
}

// tail W chunk into arbitrary stage: rows c*32..+32 of [768][256] hi/lo
__device__ __forceinline__ void w_issue_at(uint32_t sb, uint32_t wh, uint32_t wl, int c, int tid)
{
    int krow0 = c * 32;
    #pragma unroll
    for (int it = 0; it < 16; it++) {
        int cth = it * ATH + tid;
        int buf = cth >> 10, rem = cth & 1023;
        int row = rem >> 5, ch = rem & 31;
        const __nv_bfloat16* src = (buf ? g_Wcl : g_Wch) + (size_t)(krow0 + row) * D_DIM + ch * 8;
        CP16(sb + (buf ? wl : wh) + row * 512 + ((ch ^ (row & 7)) << 4), src);
    }
}

// tail A chunk (terms 1/2) into arbitrary stage: 64 rows x 32 cols hi/lo
__device__ __forceinline__ void a_issue_at(uint32_t sb, uint32_t ah, uint32_t al,
                                           int term, int koff, size_t row0, int tid)
{
    const __nv_bfloat16* aH = (term == 1 ? g_augh : g_prodh) + row0 * D_DIM;
    const __nv_bfloat16* aL = (term == 1 ? g_augl : g_prodl) + row0 * D_DIM;
    #pragma unroll
    for (int it = 0; it < 4; it++) {
        int cth = it * ATH + tid;
        int buf = cth >> 8, rem = cth & 255;
        int row = rem >> 2, cc = rem & 3;
        const __nv_bfloat16* src = (buf ? aL : aH) + (size_t)row * D_DIM + koff + cc * 8;
        CP16(sb + (buf ? al : ah) + row * 80 + cc * 16, src);
    }
}

// ---------------- fused attention + fusion kernel ----------------
__global__ __launch_bounds__(ATH)
void fused_kernel(const unsigned char* __restrict__ cmask, const float* __restrict__ c2,
                  const float* __restrict__ bf, const float* __restrict__ bg,
                  float* __restrict__ out)
{
    extern __shared__ char sm[];
    const uint32_t sb = smem_u32(sm);
    const int tid = threadIdx.x;
    const int lane = tid & 31;
    const int w = tid >> 5;              // 0..3
    const int b = blockIdx.y;
    const int q0 = blockIdx.x * BM;

    const int g  = lane >> 2;
    const int t4 = lane & 3;
    const int swz = lane & 7;
    const int r1 = (lane & 7) + 8 * ((lane >> 3) & 1);
    const int r2 = (lane & 7) + 8 * ((lane >> 4) & 1);
    const int s1 = (lane >> 3) & 1;
    const int s2 = (lane >> 4) & 1;

    const __nv_bfloat16* k1h = g_c1h + (size_t)b * L_DIM * D_DIM;
    const __nv_bfloat16* k1l = g_c1l + (size_t)b * L_DIM * D_DIM;

    // prefetch K tile 0 before preamble
    k_issue(sb, 0, tid, k1h, k1l);
    CP_COMMIT();

    // ---- preamble: ballots, gates, bf, c2 -> Q hi/lo (inline split) ----
    {
        const unsigned char* mb = cmask + (size_t)b * L_DIM;
        #pragma unroll
        for (int k = 0; k < 16; k++) {
            int word = w * 16 + k;
            int mv = (mb[word * 32 + lane] != 0);
            unsigned bal = __ballot_sync(0xffffffffu, mv);
            if (lane == 0) ((uint32_t*)(sm + SMSK))[word] = bal;
        }
        float* gs = (float*)(sm + SG);
        for (int i = tid; i < 256; i += ATH) {
            gs[i] = g_ga[i];
            gs[256 + i] = g_gb[i];
            gs[512 + i] = g_gc[i];
        }
        float* bfs = (float*)(sm + SBF);
        bfs[tid] = bf[tid];
        bfs[tid + 128] = bf[tid + 128];

        const float* c2b = c2 + ((size_t)b * L_DIM + q0) * D_DIM;
        #pragma unroll 4
        for (int it = 0; it < 32; it++) {
            int f = it * ATH + tid;          // float4 index 0..4095
            int row = f >> 6, fc = f & 63;   // row 0..63
            float4 v = *(const float4*)(c2b + (size_t)row * D_DIM + fc * 4);
            uint32_t h01 = packbf(v.y, v.x);
            uint32_t h23 = packbf(v.w, v.z);
            float hx = __uint_as_float(h01 << 16);
            float hy = __uint_as_float(h01 & 0xFFFF0000u);
            float hz = __uint_as_float(h23 << 16);
            float hw = __uint_as_float(h23 & 0xFFFF0000u);
            uint32_t l01 = packbf(v.y - hy, v.x - hx);
            uint32_t l23 = packbf(v.w - hw, v.z - hz);
            int ch = fc >> 1, half = fc & 1;
            uint32_t off = (uint32_t)(row * 512 + ((ch ^ (row & 7)) << 4) + half * 8);
            *(uint2*)(sm + SQH + off) = make_uint2(h01, h23);
            *(uint2*)(sm + SQL + off) = make_uint2(l01, l23);
        }
    }

    const uint32_t aQh = sb + SQH + (uint32_t)(16 * w + r1) * 512;
    const uint32_t aQl = sb + SQL + (uint32_t)(16 * w + r1) * 512;

    float O[32][4];
    #pragma unroll
    for (int n = 0; n < 32; n++)
        #pragma unroll
        for (int q = 0; q < 4; q++) O[n][q] = 0.f;
    float lac0 = 0.f, lac1 = 0.f;

    const int rg = q0 + 16 * w + g;
    const int myblk = (q0 + 16 * w) >> 5;

    // ================= attention mainloop (single K buffer, sibling-CTA overlap) ====
    #pragma unroll 1
    for (int t = 0; t < NTILE; t++) {
        const int j0 = t * BN;
        if (t > 0) {
            __syncthreads();                  // all warps done with tile t-1
            k_issue(sb, j0, tid, k1h, k1l);
            CP_COMMIT();
        }
        CP_WAIT(0);
        __syncthreads();                      // tile t visible (and preamble for t=0)

        float S[4][4];
        #pragma unroll
        for (int n = 0; n < 4; n++)
            #pragma unroll
            for (int q = 0; q < 4; q++) S[n][q] = 0.f;

        #pragma unroll
        for (int kt = 0; kt < 16; kt++) {
            uint32_t qh[4], ql[4];
            uint32_t aoff = (uint32_t)(((2 * kt + s2) ^ swz) << 4);
            ldsm4(aQh + aoff, qh);
            ldsm4(aQl + aoff, ql);
            #pragma unroll
            for (int np = 0; np < 2; np++) {
                uint32_t bh[4], bl[4];
                uint32_t boff = (uint32_t)((16 * np + r2) * 512 + (((2 * kt + s1) ^ swz) << 4));
                ldsm4(sb + SKH + boff, bh);
                ldsm4(sb + SKL + boff, bl);
                mma16816(S[2 * np],     qh, bh);
                mma16816(S[2 * np],     qh, bl);
                mma16816(S[2 * np],     ql, bh);
                mma16816(S[2 * np + 1], qh, bh + 2);
                mma16816(S[2 * np + 1], qh, bl + 2);
                mma16816(S[2 * np + 1], ql, bh + 2);
            }
        }

        uint32_t mbits = ((const uint32_t*)(sm + SMSK))[t];
        const bool dt = (myblk == t);
        const int dg = rg - j0, dg8 = dg + 8;

        uint32_t pg[4], pg8[4], qg[4], qg8[4];
        #pragma unroll
        for (int nt = 0; nt < 4; nt++) {
            int lc = 8 * nt + 2 * t4;
            float p0 = fast_ex2(S[nt][0] * L2E + NEG_C);
            float p1 = fast_ex2(S[nt][1] * L2E + NEG_C);
            float p2 = fast_ex2(S[nt][2] * L2E + NEG_C);
            float p3 = fast_ex2(S[nt][3] * L2E + NEG_C);
            if ((mbits >> lc) & 1)       { p0 = 0.f; p2 = 0.f; }
            if ((mbits >> (lc + 1)) & 1) { p1 = 0.f; p3 = 0.f; }
            if (dt) {
                if (lc == dg)      p0 = 0.f;
                if (lc + 1 == dg)  p1 = 0.f;
                if (lc == dg8)     p2 = 0.f;
                if (lc + 1 == dg8) p3 = 0.f;
            }
            lac0 += p0 + p1;
            lac1 += p2 + p3;
            uint32_t u0 = packbf(p1, p0);
            uint32_t u1 = packbf(p3, p2);
            pg[nt] = u0; pg8[nt] = u1;
            float h0 = __uint_as_float(u0 << 16);
            float h1 = __uint_as_float(u0 & 0xFFFF0000u);
            float h2 = __uint_as_float(u1 << 16);
            float h3 = __uint_as_float(u1 & 0xFFFF0000u);
            qg[nt]  = packbf(p1 - h1, p0 - h0);
            qg8[nt] = packbf(p3 - h3, p2 - h2);
        }

        #pragma unroll
        for (int kt = 0; kt < 2; kt++) {
            uint32_t ah[4] = {pg[2 * kt], pg8[2 * kt], pg[2 * kt + 1], pg8[2 * kt + 1]};
            uint32_t al[4] = {qg[2 * kt], qg8[2 * kt], qg[2 * kt + 1], qg8[2 * kt + 1]};
            #pragma unroll
            for (int np = 0; np < 16; np++) {
                uint32_t bh[4], bl[4];
                uint32_t boff = (uint32_t)((16 * kt + r1) * 512 + (((2 * np + s2) ^ swz) << 4));
                ldsm4t(sb + SKH + boff, bh);
                ldsm4t(sb + SKL + boff, bl);
                mma16816(O[2 * np],     ah, bh);
                mma16816(O[2 * np],     ah, bl);
                mma16816(O[2 * np],     al, bh);
                mma16816(O[2 * np + 1], ah, bh + 2);
                mma16816(O[2 * np + 1], ah, bl + 2);
                mma16816(O[2 * np + 1], al, bh + 2);
            }
        }
    }

    // ---- prefetch tail W chunk 0 (overlaps entire attention epilogue) ----
    __syncthreads();                       // all warps done reading K region
    w_issue_at(sb, SKH, SKL, 0, tid);
    CP_COMMIT();

    // ================= attention epilogue =================
    float l0 = lac0, l1 = lac1;
    l0 += __shfl_xor_sync(0xffffffffu, l0, 1);
    l0 += __shfl_xor_sync(0xffffffffu, l0, 2);
    l1 += __shfl_xor_sync(0xffffffffu, l1, 1);
    l1 += __shfl_xor_sync(0xffffffffu, l1, 2);
    float inv0 = 1.0f / l0, inv1 = 1.0f / l1;

    const size_t row0 = (size_t)b * L_DIM + q0;
    const size_t r0e = ((size_t)b * L_DIM + rg) * D_DIM;
    const size_t r1e = r0e + 8 * D_DIM;
    const float* c2r0 = c2 + r0e;
    const float* c2r1 = c2 + r1e;
    uint32_t* augh32 = (uint32_t*)g_augh;
    uint32_t* augl32 = (uint32_t*)g_augl;
    uint32_t* prodh32 = (uint32_t*)g_prodh;
    uint32_t* prodl32 = (uint32_t*)g_prodl;
    const float* gs = (const float*)(sm + SG);
    float gate0 = 0.f, gate1 = 0.f;

    #pragma unroll
    for (int nt = 0; nt < 32; nt++) {
        int col = 8 * nt + 2 * t4;
        float a0 = O[nt][0] * inv0, a1 = O[nt][1] * inv0;
        float b0 = O[nt][2] * inv1, b1 = O[nt][3] * inv1;
        float2 x0 = *(const float2*)(c2r0 + col);
        float2 x1 = *(const float2*)(c2r1 + col);
        float p0 = x0.x * a0, p1 = x0.y * a1;
        float p2 = x1.x * b0, p3 = x1.y * b1;
        float ga0 = gs[col], ga1 = gs[col + 1];
        float gb0 = gs[256 + col], gb1 = gs[257 + col];
        float gc0 = gs[512 + col], gc1 = gs[513 + col];
        gate0 += x0.x * ga0 + x0.y * ga1 + a0 * gb0 + a1 * gb1 + p0 * gc0 + p1 * gc1;
        gate1 += x1.x * ga0 + x1.y * ga1 + b0 * gb0 + b1 * gb1 + p2 * gc0 + p3 * gc1;

        uint32_t ah = packbf(a1, a0);
        float ah0 = __uint_as_float(ah << 16), ah1 = __uint_as_float(ah & 0xFFFF0000u);
        uint32_t alw = packbf(a1 - ah1, a0 - ah0);
        uint32_t bh = packbf(b1, b0);
        float bh0 = __uint_as_float(bh << 16), bh1 = __uint_as_float(bh & 0xFFFF0000u);
        uint32_t blw = packbf(b1 - bh1, b0 - bh0);
        uint32_t ph = packbf(p1, p0);
        float ph0 = __uint_as_float(ph << 16), ph1 = __uint_as_float(ph & 0xFFFF0000u);
        uint32_t plw = packbf(p1 - ph1, p0 - ph0);
        uint32_t ph2 = packbf(p3, p2);
        float pc0 = __uint_as_float(ph2 << 16), pc1 = __uint_as_float(ph2 & 0xFFFF0000u);
        uint32_t plw2 = packbf(p3 - pc1, p2 - pc0);

        size_t i0 = (r0e + col) >> 1, i1 = (r1e + col) >> 1;
        augh32[i0] = ah;   augl32[i0] = alw;
        augh32[i1] = bh;   augl32[i1] = blw;
        prodh32[i0] = ph;  prodl32[i0] = plw;
        prodh32[i1] = ph2; prodl32[i1] = plw2;
    }

    gate0 += __shfl_xor_sync(0xffffffffu, gate0, 1);
    gate0 += __shfl_xor_sync(0xffffffffu, gate0, 2);
    gate1 += __shfl_xor_sync(0xffffffffu, gate1, 1);
    gate1 += __shfl_xor_sync(0xffffffffu, gate1, 2);

    // ================= fusion GEMM tail (reuse O as accumulator) =================
    #pragma unroll
    for (int n = 0; n < 32; n++)
        #pragma unroll
        for (int q = 0; q < 4; q++) O[n][q] = 0.f;

    // ---- term 0 (c = 0..7): A = c2 from Q smem, W single-buffered in stage0 ----
    #pragma unroll 1
    for (int c = 0; c < 8; c++) {
        CP_WAIT(0);
        __syncthreads();
        #pragma unroll
        for (int kt = 0; kt < 2; kt++) {
            uint32_t ah[4], al[4];
            uint32_t aoff = (uint32_t)(((2 * (2 * c + kt) + s2) ^ swz) << 4);
            ldsm4(aQh + aoff, ah);
            ldsm4(aQl + aoff, al);
            #pragma unroll
            for (int np = 0; np < 16; np++) {
                uint32_t bh[4], bl[4];
                uint32_t boff = (uint32_t)((16 * kt + r1) * 512 + (((2 * np + s2) ^ swz) << 4));
                ldsm4t(sb + SKH + boff, bh);
                ldsm4t(sb + SKL + boff, bl);
                mma16816(O[2 * np],     ah, bh);
                mma16816(O[2 * np],     ah, bl);
                mma16816(O[2 * np],     al, bh);
                mma16816(O[2 * np + 1], ah, bh + 2);
                mma16816(O[2 * np + 1], ah, bl + 2);
                mma16816(O[2 * np + 1], al, bh + 2);
            }
        }
        __syncthreads();
        if (c < 7) { w_issue_at(sb, SKH, SKL, c + 1, tid); CP_COMMIT(); }
    }

    // ---- terms 1/2 (c = 8..23): 2-stage pipeline; stage1 lives in dead Q region ----
    // warmup: chunk 8 -> stage1, chunk 9 -> stage0
    w_issue_at(sb, ST1_WH, ST1_WL, 8, tid);
    a_issue_at(sb, ST1_AH, ST1_AL, 1, 0, row0, tid);
    CP_COMMIT();
    w_issue_at(sb, SKH, SKL, 9, tid);
    a_issue_at(sb, SA_H, SA_L, 1, 32, row0, tid);
    CP_COMMIT();

    #pragma unroll 1
    for (int c = 8; c < 24; c++) {
        if (c == 23) { CP_WAIT(0); } else { CP_WAIT(1); }
        __syncthreads();

        const uint32_t wH = (c & 1) ? (uint32_t)SKH : (uint32_t)ST1_WH;
        const uint32_t wL = (c & 1) ? (uint32_t)SKL : (uint32_t)ST1_WL;
        const uint32_t aH = (c & 1) ? (uint32_t)SA_H : (uint32_t)ST1_AH;
        const uint32_t aL = (c & 1) ? (uint32_t)SA_L : (uint32_t)ST1_AL;

        #pragma unroll
        for (int kt = 0; kt < 2; kt++) {
            uint32_t ah[4], al[4];
            uint32_t aoff = (uint32_t)((16 * w + r1) * 80 + (2 * kt + s2) * 16);
            ldsm4(sb + aH + aoff, ah);
            ldsm4(sb + aL + aoff, al);
            #pragma unroll
            for (int np = 0; np < 16; np++) {
                uint32_t bh[4], bl[4];
                uint32_t boff = (uint32_t)((16 * kt + r1) * 512 + (((2 * np + s2) ^ swz) << 4));
                ldsm4t(sb + wH + boff, bh);
                ldsm4t(sb + wL + boff, bl);
                mma16816(O[2 * np],     ah, bh);
                mma16816(O[2 * np],     ah, bl);
                mma16816(O[2 * np],     al, bh);
                mma16816(O[2 * np + 1], ah, bh + 2);
                mma16816(O[2 * np + 1], ah, bl + 2);
                mma16816(O[2 * np + 1], al, bh + 2);
            }
        }
        __syncthreads();
        if (c + 2 < 24) {
            // refill the stage just consumed with chunk c+2
            int c2n = c + 2;
            w_issue_at(sb, wH, wL, c2n, tid);
            a_issue_at(sb, aH, aL, c2n >> 3, (c2n & 7) * 32, row0, tid);
            CP_COMMIT();
        }
    }

    // ---- output epilogue ----
    const float bgv = bg[0];
    float gv0 = 1.0f / (1.0f + __expf(-(gate0 + bgv)));
    float gv1 = 1.0f / (1.0f + __expf(-(gate1 + bgv)));
    float* o0 = out + r0e;
    float* o1 = out + r1e;
    const float* bfs = (const float*)(sm + SBF);

    #pragma unroll
    for (int nt = 0; nt < 32; nt++) {
        int col = 8 * nt + 2 * t4;
        float2 bv = *(const float2*)(bfs + col);
        float2 x0 = *(const float2*)(c2r0 + col);
        float2 x1 = *(const float2*)(c2r1 + col);
        float f0 = tanhf(O[nt][0] + bv.x);
        float f1 = tanhf(O[nt][1] + bv.y);
        float f2 = tanhf(O[nt][2] + bv.x);
        float f3 = tanhf(O[nt][3] + bv.y);
        *(float2*)(o0 + col) = make_float2(gv0 * f0 + (1.f - gv0) * x0.x,
                                           gv0 * f1 + (1.f - gv0) * x0.y);
        *(float2*)(o1 + col) = make_float2(gv1 * f2 + (1.f - gv1) * x1.x,
                                           gv1 * f3 + (1.f - gv1) * x1.y);
    }
}

extern "C" void kernel_launch(void* const* d_in, const int* in_sizes, int n_in,
                              void* d_out, int out_size)
{
    (void)in_sizes; (void)n_in; (void)out_size;
    const float* c1         = (const float*)d_in[0];
    const float* c2         = (const float*)d_in[1];
    const unsigned char* cm = (const unsigned char*)d_in[2];
    const float* Wf         = (const float*)d_in[3];
    const float* bf         = (const float*)d_in[4];
    const float* Wg         = (const float*)d_in[5];
    const float* bg         = (const float*)d_in[6];
    float* out              = (float*)d_out;

    prep_convert<<<CONV_BLOCKS + 256, 256>>>(Wf, Wg, c1);

    cudaFuncSetAttribute(fused_kernel, cudaFuncAttributeMaxDynamicSharedMemorySize, ATT_SMEM);
    fused_kernel<<<dim3(L_DIM / BM, B_DIM), ATH, ATT_SMEM>>>(cm, c2, bf, bg, out);
}

// round 16
// speedup vs baseline: 1.0650x; 1.0650x over previous
#include <cuda_runtime.h>
#include <cuda_bf16.h>
#include <cstdint>
#include <math.h>

#define B_DIM 8
#define L_DIM 2048
#define D_DIM 256
#define NROW (B_DIM * L_DIM)

#define BM 64
#define BN 32
#define NTILE (L_DIM / BN)   // 64
#define ATH 128
#define L2E 1.44269504f
#define NEG_C (-57.7078016f)

// smem layout (total 112896 B = 110.25 KB -> 2 CTAs/SM)
#define SQH 0          // Q hi: 64 x 512B   (tail stage1 lives here after c=7)
#define SQL 32768      // Q lo
#define SKH 65536      // K hi 32x512 / tail stage0 W hi
#define SKL 81920      // K lo            / tail stage0 W lo
#define SMSK 98304     // 64 ballot words
#define SG   98560     // gates 3x256 f32
#define SBF  101632    // bf 256 f32
#define SA_H 102656    // tail stage0 A hi: 64 x 80B
#define SA_L 107776    // tail stage0 A lo
#define ATT_SMEM 112896

// tail stage1 (carved from dead Q region, c >= 8) — compile-time constants
#define ST1_WH 0
#define ST1_WL 16384
#define ST1_AH 32768
#define ST1_AL 37888

__device__ float g_ga[D_DIM];
__device__ float g_gb[D_DIM];
__device__ float g_gc[D_DIM];
__device__ __nv_bfloat16 g_Wch[3 * D_DIM * D_DIM];
__device__ __nv_bfloat16 g_Wcl[3 * D_DIM * D_DIM];
__device__ __nv_bfloat16 g_c1h[(size_t)NROW * D_DIM];
__device__ __nv_bfloat16 g_c1l[(size_t)NROW * D_DIM];
__device__ __nv_bfloat16 g_augh[(size_t)NROW * D_DIM];
__device__ __nv_bfloat16 g_augl[(size_t)NROW * D_DIM];
__device__ __nv_bfloat16 g_prodh[(size_t)NROW * D_DIM];
__device__ __nv_bfloat16 g_prodl[(size_t)NROW * D_DIM];

__device__ __forceinline__ uint32_t smem_u32(const void* p) {
    uint32_t a;
    asm("{ .reg .u64 t; cvta.to.shared.u64 t, %1; cvt.u32.u64 %0, t; }" : "=r"(a) : "l"(p));
    return a;
}
#define CP16(dst, src) asm volatile("cp.async.cg.shared.global [%0], [%1], 16;" :: "r"(dst), "l"(src))
#define CP_COMMIT()    asm volatile("cp.async.commit_group;" ::: "memory")
#define CP_WAIT(n)     asm volatile("cp.async.wait_group %0;" :: "n"(n) : "memory")

__device__ __forceinline__ void ldsm4(uint32_t addr, uint32_t r[4]) {
    asm volatile("ldmatrix.sync.aligned.m8n8.x4.shared.b16 {%0,%1,%2,%3}, [%4];"
        : "=r"(r[0]), "=r"(r[1]), "=r"(r[2]), "=r"(r[3]) : "r"(addr));
}
__device__ __forceinline__ void ldsm4t(uint32_t addr, uint32_t r[4]) {
    asm volatile("ldmatrix.sync.aligned.m8n8.x4.trans.shared.b16 {%0,%1,%2,%3}, [%4];"
        : "=r"(r[0]), "=r"(r[1]), "=r"(r[2]), "=r"(r[3]) : "r"(addr));
}
__device__ __forceinline__ void mma16816(float d[4], const uint32_t a[4], const uint32_t b[2]) {
    asm volatile(
        "mma.sync.aligned.m16n8k16.row.col.f32.bf16.bf16.f32 "
        "{%0,%1,%2,%3}, {%4,%5,%6,%7}, {%8,%9}, {%0,%1,%2,%3};"
        : "+f"(d[0]), "+f"(d[1]), "+f"(d[2]), "+f"(d[3])
        : "r"(a[0]), "r"(a[1]), "r"(a[2]), "r"(a[3]), "r"(b[0]), "r"(b[1]));
}
__device__ __forceinline__ float fast_ex2(float x) {
    float r;
    asm("ex2.approx.f32 %0, %1;" : "=f"(r) : "f"(x));
    return r;
}
__device__ __forceinline__ uint32_t packbf(float hi, float lo) {
    uint32_t d;
    asm("cvt.rn.bf16x2.f32 %0, %1, %2;" : "=r"(d) : "f"(hi), "f"(lo));
    return d;
}

// ---------------- merged prep + convert (one launch) ----------------
#define CONV_BLOCKS (NROW * D_DIM / 4 / 256)   // 4096
__global__ void prep_convert(const float* __restrict__ Wf, const float* __restrict__ Wg,
                             const float* __restrict__ c1)
{
    if (blockIdx.x < CONV_BLOCKS) {
        int k = blockIdx.x * 256 + threadIdx.x;
        float4 v = ((const float4*)c1)[k];
        __nv_bfloat162* oh = (__nv_bfloat162*)g_c1h;
        __nv_bfloat162* ol = (__nv_bfloat162*)g_c1l;
        __nv_bfloat16 h0 = __float2bfloat16(v.x), h1 = __float2bfloat16(v.y);
        __nv_bfloat16 h2 = __float2bfloat16(v.z), h3 = __float2bfloat16(v.w);
        oh[k * 2]     = __nv_bfloat162(h0, h1);
        oh[k * 2 + 1] = __nv_bfloat162(h2, h3);
        ol[k * 2]     = __nv_bfloat162(__float2bfloat16(v.x - __bfloat162float(h0)),
                                       __float2bfloat16(v.y - __bfloat162float(h1)));
        ol[k * 2 + 1] = __nv_bfloat162(__float2bfloat16(v.z - __bfloat162float(h2)),
                                       __float2bfloat16(v.w - __bfloat162float(h3)));
        return;
    }
    int i = (blockIdx.x - CONV_BLOCKS) * 256 + threadIdx.x;
    if (i < D_DIM * D_DIM) {
        int k = i >> 8, d = i & 255;
        float w4 = Wf[(size_t)(768 + k) * D_DIM + d];
        float wa = Wf[(size_t)k * D_DIM + d] + w4;
        float wb = Wf[(size_t)(256 + k) * D_DIM + d] - w4;
        float wc = Wf[(size_t)(512 + k) * D_DIM + d];
        float w3[3] = {wa, wb, wc};
        #pragma unroll
        for (int tmc = 0; tmc < 3; tmc++) {
            __nv_bfloat16 h = __float2bfloat16(w3[tmc]);
            size_t o = (size_t)(tmc * D_DIM + k) * D_DIM + d;
            g_Wch[o] = h;
            g_Wcl[o] = __float2bfloat16(w3[tmc] - __bfloat162float(h));
        }
    }
    if (i < D_DIM) {
        float v4 = Wg[768 + i];
        g_ga[i] = Wg[i] + v4;
        g_gb[i] = Wg[256 + i] - v4;
        g_gc[i] = Wg[512 + i];
    }
}

// ---------------- loaders ----------------
__device__ __forceinline__ void k_issue(uint32_t sb, int j0, int tid,
                                        const __nv_bfloat16* k1h, const __nv_bfloat16* k1l)
{
    #pragma unroll
    for (int it = 0; it < 16; it++) {
        int chunk = it * ATH + tid;
        int hl = chunk >> 10;
        int rem = chunk & 1023;
        int row = rem >> 5, ch = rem & 31;
        const __nv_bfloat16* src = (hl ? k1l : k1h) + ((size_t)(j0 + row)) * D_DIM + ch * 8;
        CP16(sb + (hl ? SKL : SKH) + row * 512 + ((ch ^ (row & 7)) << 4), src);
    }
}

__device__ __forceinline__ void w_issue_at(uint32_t sb, uint32_t wh, uint32_t wl, int c, int tid)
{
    int krow0 = c * 32;
    #pragma unroll
    for (int it = 0; it < 16; it++) {
        int cth = it * ATH + tid;
        int buf = cth >> 10, rem = cth & 1023;
        int row = rem >> 5, ch = rem & 31;
        const __nv_bfloat16* src = (buf ? g_Wcl : g_Wch) + (size_t)(krow0 + row) * D_DIM + ch * 8;
        CP16(sb + (buf ? wl : wh) + row * 512 + ((ch ^ (row & 7)) << 4), src);
    }
}

__device__ __forceinline__ void a_issue_at(uint32_t sb, uint32_t ah, uint32_t al,
                                           int term, int koff, size_t row0, int tid)
{
    const __nv_bfloat16* aH = (term == 1 ? g_augh : g_prodh) + row0 * D_DIM;
    const __nv_bfloat16* aL = (term == 1 ? g_augl : g_prodl) + row0 * D_DIM;
    #pragma unroll
    for (int it = 0; it < 4; it++) {
        int cth = it * ATH + tid;
        int buf = cth >> 8, rem = cth & 255;
        int row = rem >> 2, cc = rem & 3;
        const __nv_bfloat16* src = (buf ? aL : aH) + (size_t)row * D_DIM + koff + cc * 8;
        CP16(sb + (buf ? al : ah) + row * 80 + cc * 16, src);
    }
}

// tail compute body with COMPILE-TIME stage offsets
#define TAIL_BODY(WH_, WL_, AH_, AL_)                                              \
    _Pragma("unroll")                                                              \
    for (int kt = 0; kt < 2; kt++) {                                               \
        uint32_t ah[4], al[4];                                                     \
        uint32_t aoff = (uint32_t)((16 * w + r1) * 80 + (2 * kt + s2) * 16);       \
        ldsm4(sb + (AH_) + aoff, ah);                                              \
        ldsm4(sb + (AL_) + aoff, al);                                              \
        _Pragma("unroll")                                                          \
        for (int np = 0; np < 16; np++) {                                          \
            uint32_t bh[4], bl[4];                                                 \
            uint32_t boff = (uint32_t)((16 * kt + r1) * 512 + (((2 * np + s2) ^ swz) << 4)); \
            ldsm4t(sb + (WH_) + boff, bh);                                         \
            ldsm4t(sb + (WL_) + boff, bl);                                         \
            mma16816(O[2 * np],     ah, bh);                                       \
            mma16816(O[2 * np],     ah, bl);                                       \
            mma16816(O[2 * np],     al, bh);                                       \
            mma16816(O[2 * np + 1], ah, bh + 2);                                   \
            mma16816(O[2 * np + 1], ah, bl + 2);                                   \
            mma16816(O[2 * np + 1], al, bh + 2);                                   \
        }                                                                          \
    }

// ---------------- fused attention + fusion kernel ----------------
__global__ __launch_bounds__(ATH)
void fused_kernel(const unsigned char* __restrict__ cmask, const float* __restrict__ c2,
                  const float* __restrict__ bf, const float* __restrict__ bg,
                  float* __restrict__ out)
{
    extern __shared__ char sm[];
    const uint32_t sb = smem_u32(sm);
    const int tid = threadIdx.x;
    const int lane = tid & 31;
    const int w = tid >> 5;              // 0..3
    const int b = blockIdx.y;
    const int q0 = blockIdx.x * BM;

    const int g  = lane >> 2;
    const int t4 = lane & 3;
    const int swz = lane & 7;
    const int r1 = (lane & 7) + 8 * ((lane >> 3) & 1);
    const int r2 = (lane & 7) + 8 * ((lane >> 4) & 1);
    const int s1 = (lane >> 3) & 1;
    const int s2 = (lane >> 4) & 1;

    const __nv_bfloat16* k1h = g_c1h + (size_t)b * L_DIM * D_DIM;
    const __nv_bfloat16* k1l = g_c1l + (size_t)b * L_DIM * D_DIM;

    // prefetch K tile 0 before preamble
    k_issue(sb, 0, tid, k1h, k1l);
    CP_COMMIT();

    // ---- preamble: ballots, gates, bf, c2 -> Q hi/lo (inline split) ----
    {
        const unsigned char* mb = cmask + (size_t)b * L_DIM;
        #pragma unroll
        for (int k = 0; k < 16; k++) {
            int word = w * 16 + k;
            int mv = (mb[word * 32 + lane] != 0);
            unsigned bal = __ballot_sync(0xffffffffu, mv);
            if (lane == 0) ((uint32_t*)(sm + SMSK))[word] = bal;
        }
        float* gs = (float*)(sm + SG);
        for (int i = tid; i < 256; i += ATH) {
            gs[i] = g_ga[i];
            gs[256 + i] = g_gb[i];
            gs[512 + i] = g_gc[i];
        }
        float* bfs = (float*)(sm + SBF);
        bfs[tid] = bf[tid];
        bfs[tid + 128] = bf[tid + 128];

        const float* c2b = c2 + ((size_t)b * L_DIM + q0) * D_DIM;
        #pragma unroll 4
        for (int it = 0; it < 32; it++) {
            int f = it * ATH + tid;          // float4 index 0..4095
            int row = f >> 6, fc = f & 63;   // row 0..63
            float4 v = *(const float4*)(c2b + (size_t)row * D_DIM + fc * 4);
            uint32_t h01 = packbf(v.y, v.x);
            uint32_t h23 = packbf(v.w, v.z);
            float hx = __uint_as_float(h01 << 16);
            float hy = __uint_as_float(h01 & 0xFFFF0000u);
            float hz = __uint_as_float(h23 << 16);
            float hw = __uint_as_float(h23 & 0xFFFF0000u);
            uint32_t l01 = packbf(v.y - hy, v.x - hx);
            uint32_t l23 = packbf(v.w - hw, v.z - hz);
            int ch = fc >> 1, half = fc & 1;
            uint32_t off = (uint32_t)(row * 512 + ((ch ^ (row & 7)) << 4) + half * 8);
            *(uint2*)(sm + SQH + off) = make_uint2(h01, h23);
            *(uint2*)(sm + SQL + off) = make_uint2(l01, l23);
        }
    }

    const uint32_t aQh = sb + SQH + (uint32_t)(16 * w + r1) * 512;
    const uint32_t aQl = sb + SQL + (uint32_t)(16 * w + r1) * 512;

    float O[32][4];
    #pragma unroll
    for (int n = 0; n < 32; n++)
        #pragma unroll
        for (int q = 0; q < 4; q++) O[n][q] = 0.f;
    float lac0 = 0.f, lac1 = 0.f;

    const int rg = q0 + 16 * w + g;
    const int myblk = (q0 + 16 * w) >> 5;

    // ================= attention mainloop (single K buffer, sibling-CTA overlap) ====
    #pragma unroll 1
    for (int t = 0; t < NTILE; t++) {
        const int j0 = t * BN;
        if (t > 0) {
            __syncthreads();                  // all warps done with tile t-1
            k_issue(sb, j0, tid, k1h, k1l);
            CP_COMMIT();
        }
        CP_WAIT(0);
        __syncthreads();                      // tile t visible (and preamble for t=0)

        float S[4][4];
        #pragma unroll
        for (int n = 0; n < 4; n++)
            #pragma unroll
            for (int q = 0; q < 4; q++) S[n][q] = 0.f;

        #pragma unroll
        for (int kt = 0; kt < 16; kt++) {
            uint32_t qh[4], ql[4];
            uint32_t aoff = (uint32_t)(((2 * kt + s2) ^ swz) << 4);
            ldsm4(aQh + aoff, qh);
            ldsm4(aQl + aoff, ql);
            #pragma unroll
            for (int np = 0; np < 2; np++) {
                uint32_t bh[4], bl[4];
                uint32_t boff = (uint32_t)((16 * np + r2) * 512 + (((2 * kt + s1) ^ swz) << 4));
                ldsm4(sb + SKH + boff, bh);
                ldsm4(sb + SKL + boff, bl);
                mma16816(S[2 * np],     qh, bh);
                mma16816(S[2 * np],     qh, bl);
                mma16816(S[2 * np],     ql, bh);
                mma16816(S[2 * np + 1], qh, bh + 2);
                mma16816(S[2 * np + 1], qh, bl + 2);
                mma16816(S[2 * np + 1], ql, bh + 2);
            }
        }

        uint32_t mbits = ((const uint32_t*)(sm + SMSK))[t];
        const bool dt = (myblk == t);
        const int dg = rg - j0, dg8 = dg + 8;

        uint32_t pg[4], pg8[4], qg[4], qg8[4];
        #pragma unroll
        for (int nt = 0; nt < 4; nt++) {
            int lc = 8 * nt + 2 * t4;
            float p0 = fast_ex2(S[nt][0] * L2E + NEG_C);
            float p1 = fast_ex2(S[nt][1] * L2E + NEG_C);
            float p2 = fast_ex2(S[nt][2] * L2E + NEG_C);
            float p3 = fast_ex2(S[nt][3] * L2E + NEG_C);
            if ((mbits >> lc) & 1)       { p0 = 0.f; p2 = 0.f; }
            if ((mbits >> (lc + 1)) & 1) { p1 = 0.f; p3 = 0.f; }
            if (dt) {
                if (lc == dg)      p0 = 0.f;
                if (lc + 1 == dg)  p1 = 0.f;
                if (lc == dg8)     p2 = 0.f;
                if (lc + 1 == dg8) p3 = 0.f;
            }
            lac0 += p0 + p1;
            lac1 += p2 + p3;
            uint32_t u0 = packbf(p1, p0);
            uint32_t u1 = packbf(p3, p2);
            pg[nt] = u0; pg8[nt] = u1;
            float h0 = __uint_as_float(u0 << 16);
            float h1 = __uint_as_float(u0 & 0xFFFF0000u);
            float h2 = __uint_as_float(u1 << 16);
            float h3 = __uint_as_float(u1 & 0xFFFF0000u);
            qg[nt]  = packbf(p1 - h1, p0 - h0);
            qg8[nt] = packbf(p3 - h3, p2 - h2);
        }

        #pragma unroll
        for (int kt = 0; kt < 2; kt++) {
            uint32_t ah[4] = {pg[2 * kt], pg8[2 * kt], pg[2 * kt + 1], pg8[2 * kt + 1]};
            uint32_t al[4] = {qg[2 * kt], qg8[2 * kt], qg[2 * kt + 1], qg8[2 * kt + 1]};
            #pragma unroll
            for (int np = 0; np < 16; np++) {
                uint32_t bh[4], bl[4];
                uint32_t boff = (uint32_t)((16 * kt + r1) * 512 + (((2 * np + s2) ^ swz) << 4));
                ldsm4t(sb + SKH + boff, bh);
                ldsm4t(sb + SKL + boff, bl);
                mma16816(O[2 * np],     ah, bh);
                mma16816(O[2 * np],     ah, bl);
                mma16816(O[2 * np],     al, bh);
                mma16816(O[2 * np + 1], ah, bh + 2);
                mma16816(O[2 * np + 1], ah, bl + 2);
                mma16816(O[2 * np + 1], al, bh + 2);
            }
        }
    }

    // ---- prefetch tail W chunk 0 (overlaps entire attention epilogue) ----
    __syncthreads();                       // all warps done reading K region
    w_issue_at(sb, SKH, SKL, 0, tid);
    CP_COMMIT();

    // ================= attention epilogue =================
    float l0 = lac0, l1 = lac1;
    l0 += __shfl_xor_sync(0xffffffffu, l0, 1);
    l0 += __shfl_xor_sync(0xffffffffu, l0, 2);
    l1 += __shfl_xor_sync(0xffffffffu, l1, 1);
    l1 += __shfl_xor_sync(0xffffffffu, l1, 2);
    float inv0 = 1.0f / l0, inv1 = 1.0f / l1;

    const size_t row0 = (size_t)b * L_DIM + q0;
    const size_t r0e = ((size_t)b * L_DIM + rg) * D_DIM;
    const size_t r1e = r0e + 8 * D_DIM;
    const float* c2r0 = c2 + r0e;
    const float* c2r1 = c2 + r1e;
    uint32_t* augh32 = (uint32_t*)g_augh;
    uint32_t* augl32 = (uint32_t*)g_augl;
    uint32_t* prodh32 = (uint32_t*)g_prodh;
    uint32_t* prodl32 = (uint32_t*)g_prodl;
    const float* gs = (const float*)(sm + SG);
    float gate0 = 0.f, gate1 = 0.f;

    #pragma unroll
    for (int nt = 0; nt < 32; nt++) {
        int col = 8 * nt + 2 * t4;
        float a0 = O[nt][0] * inv0, a1 = O[nt][1] * inv0;
        float b0 = O[nt][2] * inv1, b1 = O[nt][3] * inv1;
        float2 x0 = *(const float2*)(c2r0 + col);
        float2 x1 = *(const float2*)(c2r1 + col);
        float p0 = x0.x * a0, p1 = x0.y * a1;
        float p2 = x1.x * b0, p3 = x1.y * b1;
        float ga0 = gs[col], ga1 = gs[col + 1];
        float gb0 = gs[256 + col], gb1 = gs[257 + col];
        float gc0 = gs[512 + col], gc1 = gs[513 + col];
        gate0 += x0.x * ga0 + x0.y * ga1 + a0 * gb0 + a1 * gb1 + p0 * gc0 + p1 * gc1;
        gate1 += x1.x * ga0 + x1.y * ga1 + b0 * gb0 + b1 * gb1 + p2 * gc0 + p3 * gc1;

        uint32_t ah = packbf(a1, a0);
        float ah0 = __uint_as_float(ah << 16), ah1 = __uint_as_float(ah & 0xFFFF0000u);
        uint32_t alw = packbf(a1 - ah1, a0 - ah0);
        uint32_t bh = packbf(b1, b0);
        float bh0 = __uint_as_float(bh << 16), bh1 = __uint_as_float(bh & 0xFFFF0000u);
        uint32_t blw = packbf(b1 - bh1, b0 - bh0);
        uint32_t ph = packbf(p1, p0);
        float ph0 = __uint_as_float(ph << 16), ph1 = __uint_as_float(ph & 0xFFFF0000u);
        uint32_t plw = packbf(p1 - ph1, p0 - ph0);
        uint32_t ph2 = packbf(p3, p2);
        float pc0 = __uint_as_float(ph2 << 16), pc1 = __uint_as_float(ph2 & 0xFFFF0000u);
        uint32_t plw2 = packbf(p3 - pc1, p2 - pc0);

        size_t i0 = (r0e + col) >> 1, i1 = (r1e + col) >> 1;
        augh32[i0] = ah;   augl32[i0] = alw;
        augh32[i1] = bh;   augl32[i1] = blw;
        prodh32[i0] = ph;  prodl32[i0] = plw;
        prodh32[i1] = ph2; prodl32[i1] = plw2;
    }

    gate0 += __shfl_xor_sync(0xffffffffu, gate0, 1);
    gate0 += __shfl_xor_sync(0xffffffffu, gate0, 2);
    gate1 += __shfl_xor_sync(0xffffffffu, gate1, 1);
    gate1 += __shfl_xor_sync(0xffffffffu, gate1, 2);

    // ================= fusion GEMM tail (reuse O as accumulator) =================
    #pragma unroll
    for (int n = 0; n < 32; n++)
        #pragma unroll
        for (int q = 0; q < 4; q++) O[n][q] = 0.f;

    // ---- term 0 (c = 0..7): A = c2 from Q smem, W single-buffered in stage0 ----
    #pragma unroll 1
    for (int c = 0; c < 8; c++) {
        CP_WAIT(0);
        __syncthreads();
        #pragma unroll
        for (int kt = 0; kt < 2; kt++) {
            uint32_t ah[4], al[4];
            uint32_t aoff = (uint32_t)(((2 * (2 * c + kt) + s2) ^ swz) << 4);
            ldsm4(aQh + aoff, ah);
            ldsm4(aQl + aoff, al);
            #pragma unroll
            for (int np = 0; np < 16; np++) {
                uint32_t bh[4], bl[4];
                uint32_t boff = (uint32_t)((16 * kt + r1) * 512 + (((2 * np + s2) ^ swz) << 4));
                ldsm4t(sb + SKH + boff, bh);
                ldsm4t(sb + SKL + boff, bl);
                mma16816(O[2 * np],     ah, bh);
                mma16816(O[2 * np],     ah, bl);
                mma16816(O[2 * np],     al, bh);
                mma16816(O[2 * np + 1], ah, bh + 2);
                mma16816(O[2 * np + 1], ah, bl + 2);
                mma16816(O[2 * np + 1], al, bh + 2);
            }
        }
        __syncthreads();
        if (c < 7) { w_issue_at(sb, SKH, SKL, c + 1, tid); CP_COMMIT(); }
    }

    // ---- terms 1/2 (c = 8..23): 2-stage pipeline, COMPILE-TIME stage offsets ----
    // warmup: chunk 8 -> stage1 (dead Q region), chunk 9 -> stage0
    w_issue_at(sb, ST1_WH, ST1_WL, 8, tid);
    a_issue_at(sb, ST1_AH, ST1_AL, 1, 0, row0, tid);
    CP_COMMIT();
    w_issue_at(sb, SKH, SKL, 9, tid);
    a_issue_at(sb, SA_H, SA_L, 1, 32, row0, tid);
    CP_COMMIT();

    #pragma unroll 1
    for (int cc = 8; cc < 24; cc += 2) {
        // even chunk cc -> stage1
        CP_WAIT(1);
        __syncthreads();
        TAIL_BODY(ST1_WH, ST1_WL, ST1_AH, ST1_AL)
        __syncthreads();
        if (cc + 2 < 24) {
            w_issue_at(sb, ST1_WH, ST1_WL, cc + 2, tid);
            a_issue_at(sb, ST1_AH, ST1_AL, (cc + 2) >> 3, ((cc + 2) & 7) * 32, row0, tid);
            CP_COMMIT();
        }
        // odd chunk cc+1 -> stage0
        if (cc + 1 == 23) { CP_WAIT(0); } else { CP_WAIT(1); }
        __syncthreads();
        TAIL_BODY(SKH, SKL, SA_H, SA_L)
        __syncthreads();
        if (cc + 3 < 24) {
            w_issue_at(sb, SKH, SKL, cc + 3, tid);
            a_issue_at(sb, SA_H, SA_L, (cc + 3) >> 3, ((cc + 3) & 7) * 32, row0, tid);
            CP_COMMIT();
        }
    }

    // ---- output epilogue ----
    const float bgv = bg[0];
    float gv0 = 1.0f / (1.0f + __expf(-(gate0 + bgv)));
    float gv1 = 1.0f / (1.0f + __expf(-(gate1 + bgv)));
    float* o0 = out + r0e;
    float* o1 = out + r1e;
    const float* bfs = (const float*)(sm + SBF);

    #pragma unroll
    for (int nt = 0; nt < 32; nt++) {
        int col = 8 * nt + 2 * t4;
        float2 bv = *(const float2*)(bfs + col);
        float2 x0 = *(const float2*)(c2r0 + col);
        float2 x1 = *(const float2*)(c2r1 + col);
        float f0 = tanhf(O[nt][0] + bv.x);
        float f1 = tanhf(O[nt][1] + bv.y);
        float f2 = tanhf(O[nt][2] + bv.x);
        float f3 = tanhf(O[nt][3] + bv.y);
        *(float2*)(o0 + col) = make_float2(gv0 * f0 + (1.f - gv0) * x0.x,
                                           gv0 * f1 + (1.f - gv0) * x0.y);
        *(float2*)(o1 + col) = make_float2(gv1 * f2 + (1.f - gv1) * x1.x,
                                           gv1 * f3 + (1.f - gv1) * x1.y);
    }
}

extern "C" void kernel_launch(void* const* d_in, const int* in_sizes, int n_in,
                              void* d_out, int out_size)
{
    (void)in_sizes; (void)n_in; (void)out_size;
    const float* c1         = (const float*)d_in[0];
    const float* c2         = (const float*)d_in[1];
    const unsigned char* cm = (const unsigned char*)d_in[2];
    const float* Wf         = (const float*)d_in[3];
    const float* bf         = (const float*)d_in[4];
    const float* Wg         = (const float*)d_in[5];
    const float* bg         = (const float*)d_in[6];
    float* out              = (float*)d_out;

    prep_convert<<<CONV_BLOCKS + 256, 256>>>(Wf, Wg, c1);

    cudaFuncSetAttribute(fused_kernel, cudaFuncAttributeMaxDynamicSharedMemorySize, ATT_SMEM);
    fused_kernel<<<dim3(L_DIM / BM, B_DIM), ATH, ATT_SMEM>>>(cm, c2, bf, bg, out);
}